// round 7
// baseline (speedup 1.0000x reference)
#include <cuda_runtime.h>

#define T_LEN 131072
#define B_ROWS 96
#define CHUNK 64
#define WARM 32
#define CPR (T_LEN / CHUNK)                 /* 2048 chunks per row */
#define TPB 128
#define NWARP (TPB / 32)                    /* 4 */
#define CH_PER_WARP 64                      /* 2 packed chunks per lane */
#define WARPS_PER_ROW (CPR / CH_PER_WARP)   /* 32 */
#define TOTAL_WARPS (B_ROWS * WARPS_PER_ROW)/* 3072 */
#define GRID (TOTAL_WARPS / NWARP)          /* 768 */
#define WIN 16                              /* samples per window */
#define NWIN 6                              /* 2 warmup + 4 main */
#define TSTRIDE 5                           /* float4 row stride (conflict-free) */

// ---------------------------------------------------------------------------
// Compile-time Butterworth(6, wn=1/6): exact port of the reference numpy path.
// ---------------------------------------------------------------------------
constexpr double csqrt(double x) {
    double g = x;
    for (int i = 0; i < 200; ++i) g = 0.5 * (g + x / g);
    return g;
}
constexpr double SQ2 = csqrt(2.0);
constexpr double SQ3 = csqrt(3.0);
constexpr double SQ6 = csqrt(6.0);
constexpr double WRP = 4.0 * (2.0 - SQ3);          // 4*tan(pi/12)
constexpr double C12 = (SQ6 + SQ2) / 4.0;
constexpr double S12 = (SQ6 - SQ2) / 4.0;
constexpr double C45 = SQ2 / 2.0;

constexpr double P1R = -WRP * C12, P1I = WRP * S12;
constexpr double P2R = -WRP * C45, P2I = WRP * C45;
constexpr double P3R = -WRP * S12, P3I = WRP * C12;

constexpr double DEN1 = (4.0 - P1R) * (4.0 - P1R) + P1I * P1I;
constexpr double DEN2 = (4.0 - P2R) * (4.0 - P2R) + P2I * P2I;
constexpr double DEN3 = (4.0 - P3R) * (4.0 - P3R) + P3I * P3I;

constexpr double RZ1 = ((4.0 + P1R) * (4.0 - P1R) - P1I * P1I) / DEN1;
constexpr double IZ1 = 8.0 * P1I / DEN1;
constexpr double RZ2 = ((4.0 + P2R) * (4.0 - P2R) - P2I * P2I) / DEN2;
constexpr double IZ2 = 8.0 * P2I / DEN2;
constexpr double RZ3 = ((4.0 + P3R) * (4.0 - P3R) - P3I * P3I) / DEN3;
constexpr double IZ3 = 8.0 * P3I / DEN3;

constexpr double W2 = WRP * WRP;
constexpr double KZ = (W2 * W2 * W2) / (DEN1 * DEN2 * DEN3);

constexpr double CC1 = 2.0 * RZ1, MM1 = RZ1 * RZ1 + IZ1 * IZ1;
constexpr double CC2 = 2.0 * RZ2, MM2 = RZ2 * RZ2 + IZ2 * IZ2;
constexpr double CC3 = 2.0 * RZ3, MM3 = RZ3 * RZ3 + IZ3 * IZ3;

constexpr double Q0 = 1.0;
constexpr double Q1 = -(CC1 + CC2);
constexpr double Q2 = MM1 + MM2 + CC1 * CC2;
constexpr double Q3 = -(CC1 * MM2 + CC2 * MM1);
constexpr double Q4 = MM1 * MM2;
constexpr double A1 = Q1 - CC3 * Q0;
constexpr double A2 = Q2 - CC3 * Q1 + MM3 * Q0;
constexpr double A3 = Q3 - CC3 * Q2 + MM3 * Q1;
constexpr double A4 = Q4 - CC3 * Q3 + MM3 * Q2;
constexpr double A5 = -CC3 * Q4 + MM3 * Q3;
constexpr double A6 = MM3 * Q4;

constexpr float FB0 = (float)(KZ * 1.0);
constexpr float FB1 = (float)(KZ * 6.0);
constexpr float FB2 = (float)(KZ * 15.0);
constexpr float FB3 = (float)(KZ * 20.0);
constexpr float FNA1 = -(float)A1;
constexpr float FNA2 = -(float)A2;
constexpr float FNA3 = -(float)A3;
constexpr float FNA4 = -(float)A4;
constexpr float FNA5 = -(float)A5;
constexpr float FNA6 = -(float)A6;
constexpr float INV_TOTAL = (float)(1.0 / ((double)B_ROWS * (double)T_LEN));

// ---- packed f32x2 helpers (double used as b64 carrier) ----
__device__ __forceinline__ double ffma2(double a, double b, double c) {
    double r;
    asm("fma.rn.f32x2 %0, %1, %2, %3;" : "=d"(r) : "d"(a), "d"(b), "d"(c));
    return r;
}
__device__ __forceinline__ double fmul2(double a, double b) {
    double r;
    asm("mul.rn.f32x2 %0, %1, %2;" : "=d"(r) : "d"(a), "d"(b));
    return r;
}
__device__ __forceinline__ double fsub2(double a, double b) {
    double r;
    asm("sub.rn.f32x2 %0, %1, %2;" : "=d"(r) : "d"(a), "d"(b));
    return r;
}
__device__ __forceinline__ double pack2(float lo, float hi) {
    double r;
    asm("mov.b64 %0, {%1, %2};" : "=d"(r) : "f"(lo), "f"(hi));
    return r;
}
__device__ __forceinline__ void unpack2(double v, float& lo, float& hi) {
    asm("mov.b64 {%0, %1}, %2;" : "=f"(lo), "=f"(hi) : "d"(v));
}
__device__ __forceinline__ void absadd2(double& acc, double y) {
    asm("{\n\t"
        ".reg .b64 t;\n\t"
        "and.b64 t, %1, 0x7FFFFFFF7FFFFFFF;\n\t"
        "add.rn.f32x2 %0, %0, t;\n\t"
        "}" : "+d"(acc) : "d"(y));
}
__device__ __forceinline__ double clear_lo(double v) {
    double r;
    asm("and.b64 %0, %1, 0xFFFFFFFF00000000;" : "=d"(r) : "d"(v));
    return r;
}

__global__ void __launch_bounds__(TPB, 4) lp_mae_kernel(
    const float* __restrict__ outp, const float* __restrict__ tgtp,
    float* __restrict__ result)
{
    // Per-warp tile: 64 chunk-rows x (4 data float4 + 1 pad) = 5120B.
    __shared__ float4 tile4[NWARP][CH_PER_WARP * TSTRIDE];

    int lane = threadIdx.x & 31;
    int warp = threadIdx.x >> 5;
    int gwarp = blockIdx.x * NWARP + warp;
    int row = gwarp >> 5;                    // / WARPS_PER_ROW
    int wc  = gwarp & 31;                    // warp index within row
    int wbase = row * T_LEN + wc * (CH_PER_WARP * CHUNK);

    float4* mytile = tile4[warp];
    int rowA = lane * TSTRIDE;               // chunk lane (float4 units)
    int rowB = (lane + 32) * TSTRIDE;        // chunk lane+32

    // Staging mapping (verified conflict-free with TSTRIDE=5):
    //   wst4 = lane>>3 (float4 index 0..3 within 16-sample window)
    //   wsc  = lane&7  (sub-chunk 0..7); j-iter covers chunks j*8+wsc
    int wst4 = lane >> 3;
    int wsc  = lane & 7;
    int wst4_4 = wst4 * 4;
    // window k address: sbase + k*WIN + j*(8*CHUNK)
    int sbase = wbase + wsc * CHUNK + wst4_4 - WARM;
    bool clamp = (wbase == 0);               // warp-uniform; row0/chunk0 head only

    // Packed coefficients (b-symmetry: b6=b0, b5=b1, b4=b2 share registers)
    const double cb0 = pack2(FB0, FB0), cb1 = pack2(FB1, FB1);
    const double cb2 = pack2(FB2, FB2), cb3 = pack2(FB3, FB3);
    const double ca1 = pack2(FNA1, FNA1), ca2 = pack2(FNA2, FNA2);
    const double ca3 = pack2(FNA3, FNA3), ca4 = pack2(FNA4, FNA4);
    const double ca5 = pack2(FNA5, FNA5), ca6 = pack2(FNA6, FNA6);

    const double dzero = pack2(0.f, 0.f);
    double z0 = dzero, z1 = dzero, z2 = dzero, z3 = dzero, z4 = dzero, z5 = dzero;
    double s2 = dzero;
    double y2;

    // Packed DF2T step (two independent chains per lane)
#define IIR_STEP2(XLO, XHI) do { \
        double x2_ = pack2((XLO), (XHI)); \
        y2 = ffma2(cb0, x2_, z0); \
        z0 = ffma2(ca1, y2, ffma2(cb1, x2_, z1)); \
        z1 = ffma2(ca2, y2, ffma2(cb2, x2_, z2)); \
        z2 = ffma2(ca3, y2, ffma2(cb3, x2_, z3)); \
        z3 = ffma2(ca4, y2, ffma2(cb2, x2_, z4)); \
        z4 = ffma2(ca5, y2, ffma2(cb1, x2_, z5)); \
        z5 = ffma2(ca6, y2, fmul2(cb0, x2_)); \
    } while (0)

    // Prefetch window K's 8 diff-double2s into registers (LDGs issue early;
    // consumed only at the NEXT window's STS -> latency hidden by compute).
#define PREFETCH(P, K) do { \
        _Pragma("unroll") \
        for (int j = 0; j < 8; ++j) { \
            int g = sbase + (K) * WIN + j * (8 * CHUNK); \
            if (clamp) g = max(g, wst4_4); \
            double2 o2_ = *(const double2*)(outp + g); \
            double2 t2_ = *(const double2*)(tgtp + g); \
            (P)[j].x = fsub2(o2_.x, t2_.x); \
            (P)[j].y = fsub2(o2_.y, t2_.y); \
        } \
    } while (0)

    double2 P[8], Q[8];
    PREFETCH(P, 0);

    #pragma unroll
    for (int k = 0; k < NWIN; ++k) {
        // Commit prefetched window k to the tile (data already in regs).
        #pragma unroll
        for (int j = 0; j < 8; ++j)
            *(double2*)&mytile[(j * 8 + wsc) * TSTRIDE + wst4] = P[j];
        __syncwarp();

        // Kick off window k+1's loads before computing window k.
        if (k + 1 < NWIN) PREFETCH(Q, k + 1);

        // Consume window k: 4 float4 per chain.
        #pragma unroll
        for (int i = 0; i < 4; ++i) {
            float4 a = mytile[rowA + i];
            float4 b = mytile[rowB + i];
            if (k < 2) {                     // warmup: discard outputs
                IIR_STEP2(a.x, b.x);
                IIR_STEP2(a.y, b.y);
                IIR_STEP2(a.z, b.z);
                IIR_STEP2(a.w, b.w);
            } else {                          // main: accumulate |y|
                IIR_STEP2(a.x, b.x); absadd2(s2, y2);
                IIR_STEP2(a.y, b.y); absadd2(s2, y2);
                IIR_STEP2(a.z, b.z); absadd2(s2, y2);
                IIR_STEP2(a.w, b.w); absadd2(s2, y2);
            }
        }

        // After warmup: row's chunk 0 (lo half, lane 0 of first warp) = zero init.
        if (k == 1 && wc == 0 && lane == 0) {
            z0 = clear_lo(z0); z1 = clear_lo(z1); z2 = clear_lo(z2);
            z3 = clear_lo(z3); z4 = clear_lo(z4); z5 = clear_lo(z5);
        }
        __syncwarp();

        #pragma unroll
        for (int j = 0; j < 8; ++j) P[j] = Q[j];
    }
#undef IIR_STEP2
#undef PREFETCH

    float slo, shi;
    unpack2(s2, slo, shi);
    float s = slo + shi;

    // Warp reduce
    #pragma unroll
    for (int off = 16; off; off >>= 1)
        s += __shfl_down_sync(0xffffffffu, s, off);

    __shared__ float ssum[NWARP];
    if (lane == 0) ssum[warp] = s;
    __syncthreads();
    if (threadIdx.x == 0) {
        float tot = 0.f;
        #pragma unroll
        for (int i = 0; i < NWARP; ++i) tot += ssum[i];
        atomicAdd(result, tot * INV_TOTAL);
    }
}

extern "C" void kernel_launch(void* const* d_in, const int* in_sizes, int n_in,
                              void* d_out, int out_size)
{
    (void)in_sizes; (void)n_in; (void)out_size;
    const float* outp = (const float*)d_in[0];
    const float* tgtp = (const float*)d_in[1];
    float* res = (float*)d_out;

    cudaMemsetAsync(res, 0, sizeof(float));
    lp_mae_kernel<<<GRID, TPB>>>(outp, tgtp, res);
}

// round 8
// speedup vs baseline: 1.9472x; 1.9472x over previous
#include <cuda_runtime.h>

#define T_LEN 131072
#define B_ROWS 96
#define CHUNK 32
#define WARM 32
#define CPR (T_LEN / CHUNK)                 /* 4096 chunks per row */
#define TPB 128
#define NWARP (TPB / 32)                    /* 4 */
#define CH_PER_WARP 64                      /* 2 packed chunks per lane */
#define WARPS_PER_ROW (CPR / CH_PER_WARP)   /* 64 */
#define TOTAL_WARPS (B_ROWS * WARPS_PER_ROW)/* 6144 */
#define GRID (TOTAL_WARPS / NWARP)          /* 1536 */
#define SPAN (CH_PER_WARP * CHUNK)          /* 2048 floats per warp */
#define REG4 ((WARM + SPAN) / 4)            /* 520 float4 staged */
#define TSTRIDE 9                           /* float4 row stride (conflict-free) */

// ---------------------------------------------------------------------------
// Compile-time Butterworth(6, wn=1/6): exact port of the reference numpy path.
// ---------------------------------------------------------------------------
constexpr double csqrt(double x) {
    double g = x;
    for (int i = 0; i < 200; ++i) g = 0.5 * (g + x / g);
    return g;
}
constexpr double SQ2 = csqrt(2.0);
constexpr double SQ3 = csqrt(3.0);
constexpr double SQ6 = csqrt(6.0);
constexpr double WRP = 4.0 * (2.0 - SQ3);          // 4*tan(pi/12)
constexpr double C12 = (SQ6 + SQ2) / 4.0;
constexpr double S12 = (SQ6 - SQ2) / 4.0;
constexpr double C45 = SQ2 / 2.0;

constexpr double P1R = -WRP * C12, P1I = WRP * S12;
constexpr double P2R = -WRP * C45, P2I = WRP * C45;
constexpr double P3R = -WRP * S12, P3I = WRP * C12;

constexpr double DEN1 = (4.0 - P1R) * (4.0 - P1R) + P1I * P1I;
constexpr double DEN2 = (4.0 - P2R) * (4.0 - P2R) + P2I * P2I;
constexpr double DEN3 = (4.0 - P3R) * (4.0 - P3R) + P3I * P3I;

constexpr double RZ1 = ((4.0 + P1R) * (4.0 - P1R) - P1I * P1I) / DEN1;
constexpr double IZ1 = 8.0 * P1I / DEN1;
constexpr double RZ2 = ((4.0 + P2R) * (4.0 - P2R) - P2I * P2I) / DEN2;
constexpr double IZ2 = 8.0 * P2I / DEN2;
constexpr double RZ3 = ((4.0 + P3R) * (4.0 - P3R) - P3I * P3I) / DEN3;
constexpr double IZ3 = 8.0 * P3I / DEN3;

constexpr double W2 = WRP * WRP;
constexpr double KZ = (W2 * W2 * W2) / (DEN1 * DEN2 * DEN3);

constexpr double CC1 = 2.0 * RZ1, MM1 = RZ1 * RZ1 + IZ1 * IZ1;
constexpr double CC2 = 2.0 * RZ2, MM2 = RZ2 * RZ2 + IZ2 * IZ2;
constexpr double CC3 = 2.0 * RZ3, MM3 = RZ3 * RZ3 + IZ3 * IZ3;

constexpr double Q0 = 1.0;
constexpr double Q1 = -(CC1 + CC2);
constexpr double Q2 = MM1 + MM2 + CC1 * CC2;
constexpr double Q3 = -(CC1 * MM2 + CC2 * MM1);
constexpr double Q4 = MM1 * MM2;
constexpr double A1 = Q1 - CC3 * Q0;
constexpr double A2 = Q2 - CC3 * Q1 + MM3 * Q0;
constexpr double A3 = Q3 - CC3 * Q2 + MM3 * Q1;
constexpr double A4 = Q4 - CC3 * Q3 + MM3 * Q2;
constexpr double A5 = -CC3 * Q4 + MM3 * Q3;
constexpr double A6 = MM3 * Q4;

constexpr float FB0 = (float)(KZ * 1.0);
constexpr float FB1 = (float)(KZ * 6.0);
constexpr float FB2 = (float)(KZ * 15.0);
constexpr float FB3 = (float)(KZ * 20.0);
constexpr float FNA1 = -(float)A1;
constexpr float FNA2 = -(float)A2;
constexpr float FNA3 = -(float)A3;
constexpr float FNA4 = -(float)A4;
constexpr float FNA5 = -(float)A5;
constexpr float FNA6 = -(float)A6;
constexpr float INV_TOTAL = (float)(1.0 / ((double)B_ROWS * (double)T_LEN));

// ---- packed f32x2 helpers (double used as b64 carrier) ----
__device__ __forceinline__ double ffma2(double a, double b, double c) {
    double r;
    asm("fma.rn.f32x2 %0, %1, %2, %3;" : "=d"(r) : "d"(a), "d"(b), "d"(c));
    return r;
}
__device__ __forceinline__ double fmul2(double a, double b) {
    double r;
    asm("mul.rn.f32x2 %0, %1, %2;" : "=d"(r) : "d"(a), "d"(b));
    return r;
}
__device__ __forceinline__ double fsub2(double a, double b) {
    double r;
    asm("sub.rn.f32x2 %0, %1, %2;" : "=d"(r) : "d"(a), "d"(b));
    return r;
}
__device__ __forceinline__ double pack2(float lo, float hi) {
    double r;
    asm("mov.b64 %0, {%1, %2};" : "=d"(r) : "f"(lo), "f"(hi));
    return r;
}
__device__ __forceinline__ void unpack2(double v, float& lo, float& hi) {
    asm("mov.b64 {%0, %1}, %2;" : "=f"(lo), "=f"(hi) : "d"(v));
}
__device__ __forceinline__ void absadd2(double& acc, double y) {
    asm("{\n\t"
        ".reg .b64 t;\n\t"
        "and.b64 t, %1, 0x7FFFFFFF7FFFFFFF;\n\t"
        "add.rn.f32x2 %0, %0, t;\n\t"
        "}" : "+d"(acc) : "d"(y));
}
__device__ __forceinline__ double clear_lo(double v) {
    double r;
    asm("and.b64 %0, %1, 0xFFFFFFFF00000000;" : "=d"(r) : "d"(v));
    return r;
}

__global__ void __launch_bounds__(TPB) lp_mae_kernel(
    const float* __restrict__ outp, const float* __restrict__ tgtp,
    float* __restrict__ result)
{
    // Per-warp tile: 65 rows x (8 data float4 + 1 pad) = 9360B; block 37440B.
    __shared__ float4 tile4[NWARP][65 * TSTRIDE];

    int lane = threadIdx.x & 31;
    int warp = threadIdx.x >> 5;
    int gwarp = blockIdx.x * NWARP + warp;
    int row = gwarp >> 6;                    // / WARPS_PER_ROW
    int wc  = gwarp & 63;                    // warp index within row
    int wbase = row * T_LEN + wc * SPAN;

    float4* mytile = tile4[warp];

    // Packed coefficients (b-symmetry: b6=b0, b5=b1, b4=b2)
    const double cb0 = pack2(FB0, FB0), cb1 = pack2(FB1, FB1);
    const double cb2 = pack2(FB2, FB2), cb3 = pack2(FB3, FB3);
    const double ca1 = pack2(FNA1, FNA1), ca2 = pack2(FNA2, FNA2);
    const double ca3 = pack2(FNA3, FNA3), ca4 = pack2(FNA4, FNA4);
    const double ca5 = pack2(FNA5, FNA5), ca6 = pack2(FNA6, FNA6);

    const double dzero = pack2(0.f, 0.f);
    double z0 = dzero, z1 = dzero, z2 = dzero, z3 = dzero, z4 = dzero, z5 = dzero;
    double s2 = dzero;
    double y2;

    // Packed DF2T step (two independent chains per lane)
#define IIR_STEP2(XLO, XHI) do { \
        double x2_ = pack2((XLO), (XHI)); \
        y2 = ffma2(cb0, x2_, z0); \
        z0 = ffma2(ca1, y2, ffma2(cb1, x2_, z1)); \
        z1 = ffma2(ca2, y2, ffma2(cb2, x2_, z2)); \
        z2 = ffma2(ca3, y2, ffma2(cb3, x2_, z3)); \
        z3 = ffma2(ca4, y2, ffma2(cb2, x2_, z4)); \
        z4 = ffma2(ca5, y2, ffma2(cb1, x2_, z5)); \
        z5 = ffma2(ca6, y2, fmul2(cb0, x2_)); \
    } while (0)

    // ---- Stage ONCE: contiguous region [wbase-32, wbase+2048), diffed ----
    // 520 float4 = 16 full warp iters + 8-lane tail. Fully coalesced
    // (consecutive lanes -> consecutive 16B). Tile row r holds floats
    // [32r, 32r+32) of the region; stride-9 float4 rows (conflict-free,
    // same pattern validated in R5).
    {
        bool clamp0 = (wbase == 0);          // warp-uniform (row 0, wc 0 only)
        int f = lane;
        #pragma unroll
        for (int it = 0; it < 16; ++it, f += 32) {
            int g = wbase - WARM + f * 4;
            if (clamp0) g = max(g, 0);       // head garbage; state reset below
            double2 o2 = *(const double2*)(outp + g);
            double2 t2 = *(const double2*)(tgtp + g);
            double2 d2;
            d2.x = fsub2(o2.x, t2.x);
            d2.y = fsub2(o2.y, t2.y);
            *(double2*)&mytile[(f >> 3) * TSTRIDE + (f & 7)] = d2;
        }
        if (lane < 8) {                      // tail: float4 512..519 (row 64)
            int ft = 512 + lane;
            int g = wbase - WARM + ft * 4;
            double2 o2 = *(const double2*)(outp + g);
            double2 t2 = *(const double2*)(tgtp + g);
            double2 d2;
            d2.x = fsub2(o2.x, t2.x);
            d2.y = fsub2(o2.y, t2.y);
            *(double2*)&mytile[64 * TSTRIDE + lane] = d2;
        }
        __syncwarp();
    }

    // Lane processes packed chunk pair (lane, lane+32).
    // Chunk c's warmup = tile row c; chunk c's main = tile row c+1.
    const float4* tA0 = mytile + lane * TSTRIDE;
    const float4* tB0 = mytile + (lane + 32) * TSTRIDE;

    // ---- Warmup: 32 samples, outputs discarded ----
    #pragma unroll
    for (int i = 0; i < 8; ++i) {
        float4 a = tA0[i];
        float4 b = tB0[i];
        IIR_STEP2(a.x, b.x);
        IIR_STEP2(a.y, b.y);
        IIR_STEP2(a.z, b.z);
        IIR_STEP2(a.w, b.w);
    }

    // Row's chunk 0 (lo chain of lane 0 in each row's first warp): zero init.
    if (wc == 0 && lane == 0) {
        z0 = clear_lo(z0); z1 = clear_lo(z1); z2 = clear_lo(z2);
        z3 = clear_lo(z3); z4 = clear_lo(z4); z5 = clear_lo(z5);
    }

    // ---- Main: 32 samples, accumulate |y| packed ----
    const float4* tA1 = tA0 + TSTRIDE;
    const float4* tB1 = tB0 + TSTRIDE;
    #pragma unroll
    for (int i = 0; i < 8; ++i) {
        float4 a = tA1[i];
        float4 b = tB1[i];
        IIR_STEP2(a.x, b.x); absadd2(s2, y2);
        IIR_STEP2(a.y, b.y); absadd2(s2, y2);
        IIR_STEP2(a.z, b.z); absadd2(s2, y2);
        IIR_STEP2(a.w, b.w); absadd2(s2, y2);
    }
#undef IIR_STEP2

    float slo, shi;
    unpack2(s2, slo, shi);
    float s = slo + shi;

    // Warp reduce
    #pragma unroll
    for (int off = 16; off; off >>= 1)
        s += __shfl_down_sync(0xffffffffu, s, off);

    __shared__ float ssum[NWARP];
    if (lane == 0) ssum[warp] = s;
    __syncthreads();
    if (threadIdx.x == 0) {
        float tot = 0.f;
        #pragma unroll
        for (int i = 0; i < NWARP; ++i) tot += ssum[i];
        atomicAdd(result, tot * INV_TOTAL);
    }
}

extern "C" void kernel_launch(void* const* d_in, const int* in_sizes, int n_in,
                              void* d_out, int out_size)
{
    (void)in_sizes; (void)n_in; (void)out_size;
    const float* outp = (const float*)d_in[0];
    const float* tgtp = (const float*)d_in[1];
    float* res = (float*)d_out;

    cudaMemsetAsync(res, 0, sizeof(float));
    lp_mae_kernel<<<GRID, TPB>>>(outp, tgtp, res);
}

// round 9
// speedup vs baseline: 2.0247x; 1.0398x over previous
#include <cuda_runtime.h>

#define T_LEN 131072
#define B_ROWS 96
#define CHUNK 64
#define WARM 32
#define CPR (T_LEN / CHUNK)                 /* 2048 chunks per row */
#define TPB 128
#define NWARP (TPB / 32)                    /* 4 */
#define CH_PER_WARP 64                      /* 2 packed chunks per lane */
#define WARPS_PER_ROW (CPR / CH_PER_WARP)   /* 32 */
#define TOTAL_WARPS (B_ROWS * WARPS_PER_ROW)/* 3072 */
#define GRID (TOTAL_WARPS / NWARP)          /* 768 */
#define WIN 16                              /* samples per window */
#define NWIN 6                              /* 2 warmup + 4 main */
#define TSTRIDE 5                           /* float4 row stride */

// ---------------------------------------------------------------------------
// Compile-time Butterworth(6, wn=1/6): exact port of the reference numpy path.
// ---------------------------------------------------------------------------
constexpr double csqrt(double x) {
    double g = x;
    for (int i = 0; i < 200; ++i) g = 0.5 * (g + x / g);
    return g;
}
constexpr double SQ2 = csqrt(2.0);
constexpr double SQ3 = csqrt(3.0);
constexpr double SQ6 = csqrt(6.0);
constexpr double WRP = 4.0 * (2.0 - SQ3);          // 4*tan(pi/12)
constexpr double C12 = (SQ6 + SQ2) / 4.0;
constexpr double S12 = (SQ6 - SQ2) / 4.0;
constexpr double C45 = SQ2 / 2.0;

constexpr double P1R = -WRP * C12, P1I = WRP * S12;
constexpr double P2R = -WRP * C45, P2I = WRP * C45;
constexpr double P3R = -WRP * S12, P3I = WRP * C12;

constexpr double DEN1 = (4.0 - P1R) * (4.0 - P1R) + P1I * P1I;
constexpr double DEN2 = (4.0 - P2R) * (4.0 - P2R) + P2I * P2I;
constexpr double DEN3 = (4.0 - P3R) * (4.0 - P3R) + P3I * P3I;

constexpr double RZ1 = ((4.0 + P1R) * (4.0 - P1R) - P1I * P1I) / DEN1;
constexpr double IZ1 = 8.0 * P1I / DEN1;
constexpr double RZ2 = ((4.0 + P2R) * (4.0 - P2R) - P2I * P2I) / DEN2;
constexpr double IZ2 = 8.0 * P2I / DEN2;
constexpr double RZ3 = ((4.0 + P3R) * (4.0 - P3R) - P3I * P3I) / DEN3;
constexpr double IZ3 = 8.0 * P3I / DEN3;

constexpr double W2 = WRP * WRP;
constexpr double KZ = (W2 * W2 * W2) / (DEN1 * DEN2 * DEN3);

constexpr double CC1 = 2.0 * RZ1, MM1 = RZ1 * RZ1 + IZ1 * IZ1;
constexpr double CC2 = 2.0 * RZ2, MM2 = RZ2 * RZ2 + IZ2 * IZ2;
constexpr double CC3 = 2.0 * RZ3, MM3 = RZ3 * RZ3 + IZ3 * IZ3;

constexpr double Q0 = 1.0;
constexpr double Q1 = -(CC1 + CC2);
constexpr double Q2 = MM1 + MM2 + CC1 * CC2;
constexpr double Q3 = -(CC1 * MM2 + CC2 * MM1);
constexpr double Q4 = MM1 * MM2;
constexpr double A1 = Q1 - CC3 * Q0;
constexpr double A2 = Q2 - CC3 * Q1 + MM3 * Q0;
constexpr double A3 = Q3 - CC3 * Q2 + MM3 * Q1;
constexpr double A4 = Q4 - CC3 * Q3 + MM3 * Q2;
constexpr double A5 = -CC3 * Q4 + MM3 * Q3;
constexpr double A6 = MM3 * Q4;

constexpr float FB0 = (float)(KZ * 1.0);
constexpr float FB1 = (float)(KZ * 6.0);
constexpr float FB2 = (float)(KZ * 15.0);
constexpr float FB3 = (float)(KZ * 20.0);
constexpr float FNA1 = -(float)A1;
constexpr float FNA2 = -(float)A2;
constexpr float FNA3 = -(float)A3;
constexpr float FNA4 = -(float)A4;
constexpr float FNA5 = -(float)A5;
constexpr float FNA6 = -(float)A6;
constexpr float INV_TOTAL = (float)(1.0 / ((double)B_ROWS * (double)T_LEN));

// ---- packed f32x2 helpers (double used as b64 carrier) ----
__device__ __forceinline__ double ffma2(double a, double b, double c) {
    double r;
    asm("fma.rn.f32x2 %0, %1, %2, %3;" : "=d"(r) : "d"(a), "d"(b), "d"(c));
    return r;
}
__device__ __forceinline__ double fmul2(double a, double b) {
    double r;
    asm("mul.rn.f32x2 %0, %1, %2;" : "=d"(r) : "d"(a), "d"(b));
    return r;
}
__device__ __forceinline__ double fsub2(double a, double b) {
    double r;
    asm("sub.rn.f32x2 %0, %1, %2;" : "=d"(r) : "d"(a), "d"(b));
    return r;
}
__device__ __forceinline__ double pack2(float lo, float hi) {
    double r;
    asm("mov.b64 %0, {%1, %2};" : "=d"(r) : "f"(lo), "f"(hi));
    return r;
}
__device__ __forceinline__ void unpack2(double v, float& lo, float& hi) {
    asm("mov.b64 {%0, %1}, %2;" : "=f"(lo), "=f"(hi) : "d"(v));
}
__device__ __forceinline__ void absadd2(double& acc, double y) {
    asm("{\n\t"
        ".reg .b64 t;\n\t"
        "and.b64 t, %1, 0x7FFFFFFF7FFFFFFF;\n\t"
        "add.rn.f32x2 %0, %0, t;\n\t"
        "}" : "+d"(acc) : "d"(y));
}
__device__ __forceinline__ double clear_lo(double v) {
    double r;
    asm("and.b64 %0, %1, 0xFFFFFFFF00000000;" : "=d"(r) : "d"(v));
    return r;
}

__global__ void __launch_bounds__(TPB) lp_mae_kernel(
    const float* __restrict__ outp, const float* __restrict__ tgtp,
    float* __restrict__ result)
{
    // Per-warp tile: 64 chunk-rows x (4 data float4 + 1 pad) = 5120B; block 20KB.
    __shared__ float4 tile4[NWARP][CH_PER_WARP * TSTRIDE];

    int lane = threadIdx.x & 31;
    int warp = threadIdx.x >> 5;
    int gwarp = blockIdx.x * NWARP + warp;
    int row = gwarp >> 5;                    // / WARPS_PER_ROW
    int wc  = gwarp & 31;                    // warp index within row
    int wbase = row * T_LEN + wc * (CH_PER_WARP * CHUNK);

    float4* mytile = tile4[warp];
    int rowA = lane * TSTRIDE;               // chunk lane (float4 units)
    int rowB = (lane + 32) * TSTRIDE;        // chunk lane+32

    // CORRECTED staging decomposition (R7's bug was the swap):
    //   c_sub = lane>>2 (sub-chunk 0..7), f4 = lane&3 (float4 idx 0..3).
    //   4 consecutive lanes -> one contiguous 64B segment. j covers chunks
    //   j*8 + c_sub, j = 0..7.
    int c_sub = lane >> 2;
    int f4    = lane & 3;
    // window k address: sbase + k*WIN + j*(8*CHUNK)
    int sbase = wbase + c_sub * CHUNK + f4 * 4 - WARM;
    bool clamp = (wbase == 0);               // warp-uniform; row0/chunk0 head only

    // Packed coefficients (b-symmetry: b6=b0, b5=b1, b4=b2)
    const double cb0 = pack2(FB0, FB0), cb1 = pack2(FB1, FB1);
    const double cb2 = pack2(FB2, FB2), cb3 = pack2(FB3, FB3);
    const double ca1 = pack2(FNA1, FNA1), ca2 = pack2(FNA2, FNA2);
    const double ca3 = pack2(FNA3, FNA3), ca4 = pack2(FNA4, FNA4);
    const double ca5 = pack2(FNA5, FNA5), ca6 = pack2(FNA6, FNA6);

    const double dzero = pack2(0.f, 0.f);
    double z0 = dzero, z1 = dzero, z2 = dzero, z3 = dzero, z4 = dzero, z5 = dzero;
    double s2 = dzero;
    double y2;

    // Packed DF2T step (two independent chains per lane)
#define IIR_STEP2(XLO, XHI) do { \
        double x2_ = pack2((XLO), (XHI)); \
        y2 = ffma2(cb0, x2_, z0); \
        z0 = ffma2(ca1, y2, ffma2(cb1, x2_, z1)); \
        z1 = ffma2(ca2, y2, ffma2(cb2, x2_, z2)); \
        z2 = ffma2(ca3, y2, ffma2(cb3, x2_, z3)); \
        z3 = ffma2(ca4, y2, ffma2(cb2, x2_, z4)); \
        z4 = ffma2(ca5, y2, ffma2(cb1, x2_, z5)); \
        z5 = ffma2(ca6, y2, fmul2(cb0, x2_)); \
    } while (0)

    // Prefetch window K's 8 diff-double2s into registers. LDGs issue here;
    // data is consumed only at the NEXT window's STS, so the full DRAM
    // latency hides behind the current window's FFMA2 chain.
#define PREFETCH(P, K) do { \
        _Pragma("unroll") \
        for (int j = 0; j < 8; ++j) { \
            int g = sbase + (K) * WIN + j * (8 * CHUNK); \
            if (clamp) g = max(g, 0); \
            double2 o2_ = *(const double2*)(outp + g); \
            double2 t2_ = *(const double2*)(tgtp + g); \
            (P)[j].x = fsub2(o2_.x, t2_.x); \
            (P)[j].y = fsub2(o2_.y, t2_.y); \
        } \
    } while (0)

    double2 P[8], Q[8];
    PREFETCH(P, 0);

    #pragma unroll
    for (int k = 0; k < NWIN; ++k) {
        // Commit prefetched window k (data already in regs; STS stalls only
        // on the prologue LDGs for k=0).
        #pragma unroll
        for (int j = 0; j < 8; ++j)
            *(double2*)&mytile[(j * 8 + c_sub) * TSTRIDE + f4] = P[j];
        __syncwarp();

        // Kick off window k+1's loads before computing window k.
        if (k + 1 < NWIN) PREFETCH(Q, k + 1);

        // Consume window k: 4 float4 per chain (16 samples).
        #pragma unroll
        for (int i = 0; i < 4; ++i) {
            float4 a = mytile[rowA + i];
            float4 b = mytile[rowB + i];
            if (k < 2) {                     // warmup: discard outputs
                IIR_STEP2(a.x, b.x);
                IIR_STEP2(a.y, b.y);
                IIR_STEP2(a.z, b.z);
                IIR_STEP2(a.w, b.w);
            } else {                          // main: accumulate |y|
                IIR_STEP2(a.x, b.x); absadd2(s2, y2);
                IIR_STEP2(a.y, b.y); absadd2(s2, y2);
                IIR_STEP2(a.z, b.z); absadd2(s2, y2);
                IIR_STEP2(a.w, b.w); absadd2(s2, y2);
            }
        }

        // After warmup: row's chunk 0 (lo chain, lane 0, first warp) = zero init.
        if (k == 1 && wc == 0 && lane == 0) {
            z0 = clear_lo(z0); z1 = clear_lo(z1); z2 = clear_lo(z2);
            z3 = clear_lo(z3); z4 = clear_lo(z4); z5 = clear_lo(z5);
        }
        __syncwarp();

        #pragma unroll
        for (int j = 0; j < 8; ++j) P[j] = Q[j];
    }
#undef IIR_STEP2
#undef PREFETCH

    float slo, shi;
    unpack2(s2, slo, shi);
    float s = slo + shi;

    // Warp reduce
    #pragma unroll
    for (int off = 16; off; off >>= 1)
        s += __shfl_down_sync(0xffffffffu, s, off);

    __shared__ float ssum[NWARP];
    if (lane == 0) ssum[warp] = s;
    __syncthreads();
    if (threadIdx.x == 0) {
        float tot = 0.f;
        #pragma unroll
        for (int i = 0; i < NWARP; ++i) tot += ssum[i];
        atomicAdd(result, tot * INV_TOTAL);
    }
}

extern "C" void kernel_launch(void* const* d_in, const int* in_sizes, int n_in,
                              void* d_out, int out_size)
{
    (void)in_sizes; (void)n_in; (void)out_size;
    const float* outp = (const float*)d_in[0];
    const float* tgtp = (const float*)d_in[1];
    float* res = (float*)d_out;

    cudaMemsetAsync(res, 0, sizeof(float));
    lp_mae_kernel<<<GRID, TPB>>>(outp, tgtp, res);
}

// round 10
// speedup vs baseline: 2.1613x; 1.0674x over previous
#include <cuda_runtime.h>

#define T_LEN 131072
#define B_ROWS 96
#define CHUNK 64
#define WARM 32
#define CPR (T_LEN / CHUNK)                 /* 2048 chunks per row */
#define TPB 128
#define NWARP (TPB / 32)                    /* 4 */
#define CH_PER_WARP 64                      /* 2 packed chunks per lane */
#define WARPS_PER_ROW (CPR / CH_PER_WARP)   /* 32 */
#define TOTAL_WARPS (B_ROWS * WARPS_PER_ROW)/* 3072 */
#define GRID (TOTAL_WARPS / NWARP)          /* 768 */
#define WIN 32                              /* samples per window */
#define TSTRIDE 9                           /* float4 row stride (R5-validated) */

// ---------------------------------------------------------------------------
// Compile-time Butterworth(6, wn=1/6): exact port of the reference numpy path.
// ---------------------------------------------------------------------------
constexpr double csqrt(double x) {
    double g = x;
    for (int i = 0; i < 200; ++i) g = 0.5 * (g + x / g);
    return g;
}
constexpr double SQ2 = csqrt(2.0);
constexpr double SQ3 = csqrt(3.0);
constexpr double SQ6 = csqrt(6.0);
constexpr double WRP = 4.0 * (2.0 - SQ3);          // 4*tan(pi/12)
constexpr double C12 = (SQ6 + SQ2) / 4.0;
constexpr double S12 = (SQ6 - SQ2) / 4.0;
constexpr double C45 = SQ2 / 2.0;

constexpr double P1R = -WRP * C12, P1I = WRP * S12;
constexpr double P2R = -WRP * C45, P2I = WRP * C45;
constexpr double P3R = -WRP * S12, P3I = WRP * C12;

constexpr double DEN1 = (4.0 - P1R) * (4.0 - P1R) + P1I * P1I;
constexpr double DEN2 = (4.0 - P2R) * (4.0 - P2R) + P2I * P2I;
constexpr double DEN3 = (4.0 - P3R) * (4.0 - P3R) + P3I * P3I;

constexpr double RZ1 = ((4.0 + P1R) * (4.0 - P1R) - P1I * P1I) / DEN1;
constexpr double IZ1 = 8.0 * P1I / DEN1;
constexpr double RZ2 = ((4.0 + P2R) * (4.0 - P2R) - P2I * P2I) / DEN2;
constexpr double IZ2 = 8.0 * P2I / DEN2;
constexpr double RZ3 = ((4.0 + P3R) * (4.0 - P3R) - P3I * P3I) / DEN3;
constexpr double IZ3 = 8.0 * P3I / DEN3;

constexpr double W2 = WRP * WRP;
constexpr double KZ = (W2 * W2 * W2) / (DEN1 * DEN2 * DEN3);

constexpr double CC1 = 2.0 * RZ1, MM1 = RZ1 * RZ1 + IZ1 * IZ1;
constexpr double CC2 = 2.0 * RZ2, MM2 = RZ2 * RZ2 + IZ2 * IZ2;
constexpr double CC3 = 2.0 * RZ3, MM3 = RZ3 * RZ3 + IZ3 * IZ3;

constexpr double Q0 = 1.0;
constexpr double Q1 = -(CC1 + CC2);
constexpr double Q2 = MM1 + MM2 + CC1 * CC2;
constexpr double Q3 = -(CC1 * MM2 + CC2 * MM1);
constexpr double Q4 = MM1 * MM2;
constexpr double A1 = Q1 - CC3 * Q0;
constexpr double A2 = Q2 - CC3 * Q1 + MM3 * Q0;
constexpr double A3 = Q3 - CC3 * Q2 + MM3 * Q1;
constexpr double A4 = Q4 - CC3 * Q3 + MM3 * Q2;
constexpr double A5 = -CC3 * Q4 + MM3 * Q3;
constexpr double A6 = MM3 * Q4;

constexpr float FB0 = (float)(KZ * 1.0);
constexpr float FB1 = (float)(KZ * 6.0);
constexpr float FB2 = (float)(KZ * 15.0);
constexpr float FB3 = (float)(KZ * 20.0);
constexpr float FNA1 = -(float)A1;
constexpr float FNA2 = -(float)A2;
constexpr float FNA3 = -(float)A3;
constexpr float FNA4 = -(float)A4;
constexpr float FNA5 = -(float)A5;
constexpr float FNA6 = -(float)A6;
constexpr float INV_TOTAL = (float)(1.0 / ((double)B_ROWS * (double)T_LEN));

// ---- packed f32x2 helpers (double used as b64 carrier) ----
__device__ __forceinline__ double ffma2(double a, double b, double c) {
    double r;
    asm("fma.rn.f32x2 %0, %1, %2, %3;" : "=d"(r) : "d"(a), "d"(b), "d"(c));
    return r;
}
__device__ __forceinline__ double fmul2(double a, double b) {
    double r;
    asm("mul.rn.f32x2 %0, %1, %2;" : "=d"(r) : "d"(a), "d"(b));
    return r;
}
__device__ __forceinline__ double fsub2(double a, double b) {
    double r;
    asm("sub.rn.f32x2 %0, %1, %2;" : "=d"(r) : "d"(a), "d"(b));
    return r;
}
__device__ __forceinline__ double pack2(float lo, float hi) {
    double r;
    asm("mov.b64 %0, {%1, %2};" : "=d"(r) : "f"(lo), "f"(hi));
    return r;
}
__device__ __forceinline__ void unpack2(double v, float& lo, float& hi) {
    asm("mov.b64 {%0, %1}, %2;" : "=f"(lo), "=f"(hi) : "d"(v));
}
__device__ __forceinline__ void absadd2(double& acc, double y) {
    asm("{\n\t"
        ".reg .b64 t;\n\t"
        "and.b64 t, %1, 0x7FFFFFFF7FFFFFFF;\n\t"
        "add.rn.f32x2 %0, %0, t;\n\t"
        "}" : "+d"(acc) : "d"(y));
}
__device__ __forceinline__ double clear_lo(double v) {
    double r;
    asm("and.b64 %0, %1, 0xFFFFFFFF00000000;" : "=d"(r) : "d"(v));
    return r;
}

__global__ void __launch_bounds__(TPB) lp_mae_kernel(
    const float* __restrict__ outp, const float* __restrict__ tgtp,
    float* __restrict__ result)
{
    // Per-warp tile: 64 chunk-rows x (8 data float4 + 1 pad) = 9216B.
    __shared__ float4 tile4[NWARP][CH_PER_WARP * TSTRIDE];

    int lane = threadIdx.x & 31;
    int warp = threadIdx.x >> 5;
    int gwarp = blockIdx.x * NWARP + warp;
    int row = gwarp >> 5;                    // / WARPS_PER_ROW
    int wc  = gwarp & 31;                    // warp index within row
    int wbase = row * T_LEN + wc * (CH_PER_WARP * CHUNK);

    float4* mytile = tile4[warp];
    int rowA = lane * TSTRIDE;               // chunk lane (float4 units)
    int rowB = (lane + 32) * TSTRIDE;        // chunk lane+32

    // R5-validated staging mapping: sc = lane>>3 (sub-chunk 0..3),
    // st4 = lane&7 (float4 idx 0..7). 8 consecutive lanes cover one
    // contiguous 128B segment -> 4 lines per warp-LDG (optimal).
    int sc  = lane >> 3;
    int st4 = lane & 7;
    int sbase = wbase + sc * CHUNK + st4 * 4 - WARM;
    bool clamp = (wbase == 0);               // warp-uniform; row0/chunk0 head only

    // Packed coefficients (b-symmetry: b6=b0, b5=b1, b4=b2)
    const double cb0 = pack2(FB0, FB0), cb1 = pack2(FB1, FB1);
    const double cb2 = pack2(FB2, FB2), cb3 = pack2(FB3, FB3);
    const double ca1 = pack2(FNA1, FNA1), ca2 = pack2(FNA2, FNA2);
    const double ca3 = pack2(FNA3, FNA3), ca4 = pack2(FNA4, FNA4);
    const double ca5 = pack2(FNA5, FNA5), ca6 = pack2(FNA6, FNA6);

    const double dzero = pack2(0.f, 0.f);
    double z0 = dzero, z1 = dzero, z2 = dzero, z3 = dzero, z4 = dzero, z5 = dzero;
    double s2 = dzero;
    double y2;

    // Packed DF2T step (two independent chains per lane)
#define IIR_STEP2(XLO, XHI) do { \
        double x2_ = pack2((XLO), (XHI)); \
        y2 = ffma2(cb0, x2_, z0); \
        z0 = ffma2(ca1, y2, ffma2(cb1, x2_, z1)); \
        z1 = ffma2(ca2, y2, ffma2(cb2, x2_, z2)); \
        z2 = ffma2(ca3, y2, ffma2(cb3, x2_, z3)); \
        z3 = ffma2(ca4, y2, ffma2(cb2, x2_, z4)); \
        z4 = ffma2(ca5, y2, ffma2(cb1, x2_, z5)); \
        z5 = ffma2(ca6, y2, fmul2(cb0, x2_)); \
    } while (0)

    // Load window at TOFF into the 16-double2 register buffer P.
    // LDGs issue here and retire during the compute that follows.
#define PREFETCH(TOFF, CLAMP) do { \
        _Pragma("unroll") \
        for (int j = 0; j < 16; ++j) { \
            int g = sbase + j * (4 * CHUNK) + (TOFF); \
            if (CLAMP) g = max(g, 0); \
            double2 o2_ = *(const double2*)(outp + g); \
            double2 t2_ = *(const double2*)(tgtp + g); \
            P[j].x = fsub2(o2_.x, t2_.x); \
            P[j].y = fsub2(o2_.y, t2_.y); \
        } \
    } while (0)

#define COMMIT() do { \
        _Pragma("unroll") \
        for (int j = 0; j < 16; ++j) \
            *(double2*)&mytile[(j * 4 + sc) * TSTRIDE + st4] = P[j]; \
        __syncwarp(); \
    } while (0)

    double2 P[16];

    // ---- Window 0 (warmup, toff=-32): prologue load, outputs discarded ----
    PREFETCH(-WIN, clamp);
    COMMIT();
    PREFETCH(0, false);                      // window 1 loads fly during warmup compute
    #pragma unroll
    for (int i = 0; i < 8; ++i) {
        float4 a = mytile[rowA + i];
        float4 b = mytile[rowB + i];
        IIR_STEP2(a.x, b.x);
        IIR_STEP2(a.y, b.y);
        IIR_STEP2(a.z, b.z);
        IIR_STEP2(a.w, b.w);
    }
    // Row's chunk 0 (lo chain of lane 0 in each row's first warp): zero init.
    if (wc == 0 && lane == 0) {
        z0 = clear_lo(z0); z1 = clear_lo(z1); z2 = clear_lo(z2);
        z3 = clear_lo(z3); z4 = clear_lo(z4); z5 = clear_lo(z5);
    }
    __syncwarp();

    // ---- Window 1 (main, toff=0) ----
    COMMIT();
    PREFETCH(WIN, false);                    // window 2 loads fly during compute
    #pragma unroll
    for (int i = 0; i < 8; ++i) {
        float4 a = mytile[rowA + i];
        float4 b = mytile[rowB + i];
        IIR_STEP2(a.x, b.x); absadd2(s2, y2);
        IIR_STEP2(a.y, b.y); absadd2(s2, y2);
        IIR_STEP2(a.z, b.z); absadd2(s2, y2);
        IIR_STEP2(a.w, b.w); absadd2(s2, y2);
    }
    __syncwarp();

    // ---- Window 2 (main, toff=+32) ----
    COMMIT();
    #pragma unroll
    for (int i = 0; i < 8; ++i) {
        float4 a = mytile[rowA + i];
        float4 b = mytile[rowB + i];
        IIR_STEP2(a.x, b.x); absadd2(s2, y2);
        IIR_STEP2(a.y, b.y); absadd2(s2, y2);
        IIR_STEP2(a.z, b.z); absadd2(s2, y2);
        IIR_STEP2(a.w, b.w); absadd2(s2, y2);
    }
#undef IIR_STEP2
#undef PREFETCH
#undef COMMIT

    float slo, shi;
    unpack2(s2, slo, shi);
    float s = slo + shi;

    // Warp reduce
    #pragma unroll
    for (int off = 16; off; off >>= 1)
        s += __shfl_down_sync(0xffffffffu, s, off);

    __shared__ float ssum[NWARP];
    if (lane == 0) ssum[warp] = s;
    __syncthreads();
    if (threadIdx.x == 0) {
        float tot = 0.f;
        #pragma unroll
        for (int i = 0; i < NWARP; ++i) tot += ssum[i];
        atomicAdd(result, tot * INV_TOTAL);
    }
}

extern "C" void kernel_launch(void* const* d_in, const int* in_sizes, int n_in,
                              void* d_out, int out_size)
{
    (void)in_sizes; (void)n_in; (void)out_size;
    const float* outp = (const float*)d_in[0];
    const float* tgtp = (const float*)d_in[1];
    float* res = (float*)d_out;

    cudaMemsetAsync(res, 0, sizeof(float));
    lp_mae_kernel<<<GRID, TPB>>>(outp, tgtp, res);
}

// round 11
// speedup vs baseline: 2.2435x; 1.0381x over previous
#include <cuda_runtime.h>

#define T_LEN 131072
#define B_ROWS 96
#define CHUNK 64
#define WARM 32
#define CPR (T_LEN / CHUNK)                 /* 2048 chunks per row */
#define TPB 128
#define NWARP (TPB / 32)                    /* 4 */
#define CH_PER_WARP 64                      /* 2 packed chunks per lane */
#define WARPS_PER_ROW (CPR / CH_PER_WARP)   /* 32 */
#define TOTAL_WARPS (B_ROWS * WARPS_PER_ROW)/* 3072 */
#define GRID (TOTAL_WARPS / NWARP)          /* 768 */
#define WIN 32                              /* samples per main window */

// ---------------------------------------------------------------------------
// Compile-time Butterworth(6, wn=1/6): exact port of the reference numpy path.
// ---------------------------------------------------------------------------
constexpr double csqrt(double x) {
    double g = x;
    for (int i = 0; i < 200; ++i) g = 0.5 * (g + x / g);
    return g;
}
constexpr double SQ2 = csqrt(2.0);
constexpr double SQ3 = csqrt(3.0);
constexpr double SQ6 = csqrt(6.0);
constexpr double WRP = 4.0 * (2.0 - SQ3);          // 4*tan(pi/12)
constexpr double C12 = (SQ6 + SQ2) / 4.0;
constexpr double S12 = (SQ6 - SQ2) / 4.0;
constexpr double C45 = SQ2 / 2.0;

constexpr double P1R = -WRP * C12, P1I = WRP * S12;
constexpr double P2R = -WRP * C45, P2I = WRP * C45;
constexpr double P3R = -WRP * S12, P3I = WRP * C12;

constexpr double DEN1 = (4.0 - P1R) * (4.0 - P1R) + P1I * P1I;
constexpr double DEN2 = (4.0 - P2R) * (4.0 - P2R) + P2I * P2I;
constexpr double DEN3 = (4.0 - P3R) * (4.0 - P3R) + P3I * P3I;

constexpr double RZ1 = ((4.0 + P1R) * (4.0 - P1R) - P1I * P1I) / DEN1;
constexpr double IZ1 = 8.0 * P1I / DEN1;
constexpr double RZ2 = ((4.0 + P2R) * (4.0 - P2R) - P2I * P2I) / DEN2;
constexpr double IZ2 = 8.0 * P2I / DEN2;
constexpr double RZ3 = ((4.0 + P3R) * (4.0 - P3R) - P3I * P3I) / DEN3;
constexpr double IZ3 = 8.0 * P3I / DEN3;

constexpr double W2 = WRP * WRP;
constexpr double KZ = (W2 * W2 * W2) / (DEN1 * DEN2 * DEN3);

constexpr double CC1 = 2.0 * RZ1, MM1 = RZ1 * RZ1 + IZ1 * IZ1;
constexpr double CC2 = 2.0 * RZ2, MM2 = RZ2 * RZ2 + IZ2 * IZ2;
constexpr double CC3 = 2.0 * RZ3, MM3 = RZ3 * RZ3 + IZ3 * IZ3;

constexpr double Q0 = 1.0;
constexpr double Q1 = -(CC1 + CC2);
constexpr double Q2 = MM1 + MM2 + CC1 * CC2;
constexpr double Q3 = -(CC1 * MM2 + CC2 * MM1);
constexpr double Q4 = MM1 * MM2;
constexpr double A1 = Q1 - CC3 * Q0;
constexpr double A2 = Q2 - CC3 * Q1 + MM3 * Q0;
constexpr double A3 = Q3 - CC3 * Q2 + MM3 * Q1;
constexpr double A4 = Q4 - CC3 * Q3 + MM3 * Q2;
constexpr double A5 = -CC3 * Q4 + MM3 * Q3;
constexpr double A6 = MM3 * Q4;

constexpr float FB0 = (float)(KZ * 1.0);
constexpr float FB1 = (float)(KZ * 6.0);
constexpr float FB2 = (float)(KZ * 15.0);
constexpr float FB3 = (float)(KZ * 20.0);
constexpr float FB4 = (float)(KZ * 15.0);
constexpr float FB5 = (float)(KZ * 6.0);
constexpr float FB6 = (float)(KZ * 1.0);
constexpr float FNA1 = -(float)A1;
constexpr float FNA2 = -(float)A2;
constexpr float FNA3 = -(float)A3;
constexpr float FNA4 = -(float)A4;
constexpr float FNA5 = -(float)A5;
constexpr float FNA6 = -(float)A6;
constexpr float INV_TOTAL = (float)(1.0 / ((double)B_ROWS * (double)T_LEN));

// ---- packed f32x2 helpers (double used as b64 carrier) ----
__device__ __forceinline__ double ffma2(double a, double b, double c) {
    double r;
    asm("fma.rn.f32x2 %0, %1, %2, %3;" : "=d"(r) : "d"(a), "d"(b), "d"(c));
    return r;
}
__device__ __forceinline__ double fmul2(double a, double b) {
    double r;
    asm("mul.rn.f32x2 %0, %1, %2;" : "=d"(r) : "d"(a), "d"(b));
    return r;
}
__device__ __forceinline__ double pack2(float lo, float hi) {
    double r;
    asm("mov.b64 %0, {%1, %2};" : "=d"(r) : "f"(lo), "f"(hi));
    return r;
}
__device__ __forceinline__ void unpack2(double v, float& lo, float& hi) {
    asm("mov.b64 {%0, %1}, %2;" : "=f"(lo), "=f"(hi) : "d"(v));
}
__device__ __forceinline__ void absadd2(double& acc, double y) {
    asm("{\n\t"
        ".reg .b64 t;\n\t"
        "and.b64 t, %1, 0x7FFFFFFF7FFFFFFF;\n\t"
        "add.rn.f32x2 %0, %0, t;\n\t"
        "}" : "+d"(acc) : "d"(y));
}
__device__ __forceinline__ double clear_lo(double v) {
    double r;
    asm("and.b64 %0, %1, 0xFFFFFFFF00000000;" : "=d"(r) : "d"(v));
    return r;
}

// Scratch for single-kernel reduction (overwritten every launch; counter is
// reset to 0 by the finishing block -> deterministic across graph replays).
__device__ float g_partials[GRID];
__device__ unsigned int g_done = 0;

__global__ void __launch_bounds__(TPB) lp_mae_kernel(
    const float* __restrict__ outp, const float* __restrict__ tgtp,
    float* __restrict__ result)
{
    // Per-warp tile: 64 chunk-rows x (8 data float4 + 1 pad float4) = 9216B.
    __shared__ float4 tile4[NWARP][CH_PER_WARP * 9];

    int lane = threadIdx.x & 31;
    int warp = threadIdx.x >> 5;
    int gwarp = blockIdx.x * NWARP + warp;
    int row = gwarp >> 5;                    // / WARPS_PER_ROW
    int wc  = gwarp & 31;                    // warp index within row
    int wbase = row * T_LEN + wc * (CH_PER_WARP * CHUNK);

    // Staging: lane -> (sub-chunk 0..3, float4 idx 0..7); 16 j-iters cover 64 rows.
    // 8 consecutive lanes cover one contiguous 128B line (R5-validated).
    int sc  = lane >> 3;
    int st4 = lane & 7;
    int st4_4 = st4 * 4;
    int sbase = wbase + sc * CHUNK + st4_4;

    float4* mytile = tile4[warp];
    int rowA = lane * 9;                     // chunk lane
    int rowB = (lane + 32) * 9;              // chunk lane+32

    // Packed coefficients (both halves identical)
    const double cb0 = pack2(FB0, FB0), cb1 = pack2(FB1, FB1);
    const double cb2 = pack2(FB2, FB2), cb3 = pack2(FB3, FB3);
    const double cb4 = pack2(FB4, FB4), cb5 = pack2(FB5, FB5);
    const double cb6 = pack2(FB6, FB6);
    const double ca1 = pack2(FNA1, FNA1), ca2 = pack2(FNA2, FNA2);
    const double ca3 = pack2(FNA3, FNA3), ca4 = pack2(FNA4, FNA4);
    const double ca5 = pack2(FNA5, FNA5), ca6 = pack2(FNA6, FNA6);

    const double dzero = pack2(0.f, 0.f);
    double z0 = dzero, z1 = dzero, z2 = dzero, z3 = dzero, z4 = dzero, z5 = dzero;
    double s2 = dzero;
    double y2;

    // Packed DF2T step (two independent chains, lo=chunk lane, hi=chunk lane+32)
#define IIR_STEP2(XLO, XHI) do { \
        double x2_ = pack2((XLO), (XHI)); \
        y2 = ffma2(cb0, x2_, z0); \
        z0 = ffma2(ca1, y2, ffma2(cb1, x2_, z1)); \
        z1 = ffma2(ca2, y2, ffma2(cb2, x2_, z2)); \
        z2 = ffma2(ca3, y2, ffma2(cb3, x2_, z3)); \
        z3 = ffma2(ca4, y2, ffma2(cb4, x2_, z4)); \
        z4 = ffma2(ca5, y2, ffma2(cb5, x2_, z5)); \
        z5 = ffma2(ca6, y2, fmul2(cb6, x2_)); \
    } while (0)

#define STAGE(TOFF, CLAMP) do { \
        _Pragma("unroll") \
        for (int j = 0; j < 16; ++j) { \
            int g = sbase + (j * 4) * CHUNK + (TOFF); \
            if (CLAMP) g = max(g, st4_4); \
            float4 o = *(const float4*)(outp + g); \
            float4 t = *(const float4*)(tgtp + g); \
            mytile[(j * 4 + sc) * 9 + st4] = \
                make_float4(o.x - t.x, o.y - t.y, o.z - t.z, o.w - t.w); \
        } \
        __syncwarp(); \
    } while (0)

    // ---- Warmup window (toff = -32), outputs discarded ----
    {
        bool needs_clamp = (wbase == 0);
        STAGE(-WIN, needs_clamp);
        #pragma unroll
        for (int i = 0; i < 8; ++i) {
            float4 a = mytile[rowA + i];
            float4 b = mytile[rowB + i];
            IIR_STEP2(a.x, b.x);
            IIR_STEP2(a.y, b.y);
            IIR_STEP2(a.z, b.z);
            IIR_STEP2(a.w, b.w);
        }
        __syncwarp();
    }

    // Row's chunk 0 (lo half of lane 0 in each row's first warp): zero init.
    if (wc == 0 && lane == 0) {
        z0 = clear_lo(z0); z1 = clear_lo(z1); z2 = clear_lo(z2);
        z3 = clear_lo(z3); z4 = clear_lo(z4); z5 = clear_lo(z5);
    }

    // ---- Main windows (toff = 0, +32), accumulate |y| packed ----
    #pragma unroll
    for (int w = 0; w < CHUNK / WIN; ++w) {
        STAGE(w * WIN, false);
        #pragma unroll
        for (int i = 0; i < 8; ++i) {
            float4 a = mytile[rowA + i];
            float4 b = mytile[rowB + i];
            IIR_STEP2(a.x, b.x); absadd2(s2, y2);
            IIR_STEP2(a.y, b.y); absadd2(s2, y2);
            IIR_STEP2(a.z, b.z); absadd2(s2, y2);
            IIR_STEP2(a.w, b.w); absadd2(s2, y2);
        }
        __syncwarp();
    }
#undef IIR_STEP2
#undef STAGE

    float slo, shi;
    unpack2(s2, slo, shi);
    float s = slo + shi;

    // Warp reduce
    #pragma unroll
    for (int off = 16; off; off >>= 1)
        s += __shfl_down_sync(0xffffffffu, s, off);

    __shared__ float ssum[NWARP];
    __shared__ int is_last;
    if (lane == 0) ssum[warp] = s;
    __syncthreads();
    if (threadIdx.x == 0) {
        float tot = 0.f;
        #pragma unroll
        for (int i = 0; i < NWARP; ++i) tot += ssum[i];
        g_partials[blockIdx.x] = tot;
        __threadfence();
        unsigned int t = atomicAdd(&g_done, 1u);
        is_last = (t == GRID - 1);
    }
    __syncthreads();

    // Last-arriving block: sum all partials, write d_out, reset counter.
    if (is_last) {
        float v = 0.f;
        #pragma unroll
        for (int i = 0; i < GRID / TPB; ++i)      // 6 partials per thread
            v += g_partials[threadIdx.x + i * TPB];
        #pragma unroll
        for (int off = 16; off; off >>= 1)
            v += __shfl_down_sync(0xffffffffu, v, off);
        if (lane == 0) ssum[warp] = v;
        __syncthreads();
        if (threadIdx.x == 0) {
            float tot = 0.f;
            #pragma unroll
            for (int i = 0; i < NWARP; ++i) tot += ssum[i];
            *result = tot * INV_TOTAL;
            g_done = 0;                           // reset for next replay
        }
    }
}

extern "C" void kernel_launch(void* const* d_in, const int* in_sizes, int n_in,
                              void* d_out, int out_size)
{
    (void)in_sizes; (void)n_in; (void)out_size;
    const float* outp = (const float*)d_in[0];
    const float* tgtp = (const float*)d_in[1];
    float* res = (float*)d_out;

    lp_mae_kernel<<<GRID, TPB>>>(outp, tgtp, res);
}